// round 15
// baseline (speedup 1.0000x reference)
#include <cuda_runtime.h>
#include <cuda_fp16.h>
#include <cstdint>

#define NB 8
#define NN 256
#define BN (NB*NN)          // 2048 nodes
#define HD 64
#define NL 4
#define CRANGE 3.75f        // 15.0 / 4 layers

// ---------------- device scratch ----------------
__device__ __align__(16) float g_h[BN*HD];
__device__ __align__(16) float g_H1A[BN*HD];
__device__ __align__(16) __half g_H1Bh[2][BN*HD];   // fp16: halves L1/L2 traffic in phase B
__device__ __align__(16) float g_E0[BN*NN];
__device__ __align__(16) float g_coordA[BN*3];
__device__ __align__(16) float g_coordB[BN*3];
__device__ __align__(16) float g_x0[BN*3];
__device__ __align__(16) __half g_W2h[NL][64*72];
__device__ __align__(16) __half g_C1h[NL][64*72];

__device__ __forceinline__ float tanh_ap(float x) {
    float y; asm("tanh.approx.f32 %0, %1;" : "=f"(y) : "f"(x)); return y;
}
__device__ __forceinline__ float silu_h(float x) {
    return x * fmaf(0.5f, tanh_ap(0.5f * x), 0.5f);
}
__device__ __forceinline__ float sigm_h(float x) {
    return fmaf(0.5f, tanh_ap(0.5f * x), 0.5f);
}
__device__ __forceinline__ float siluf(float x) {
    return __fdividef(x, 1.f + __expf(-x));
}

// ---------------- HMMA helpers ----------------
#define LDSM4(r0,r1,r2,r3, addr) \
    asm volatile("ldmatrix.sync.aligned.m8n8.x4.shared.b16 {%0,%1,%2,%3}, [%4];" \
        : "=r"(r0), "=r"(r1), "=r"(r2), "=r"(r3) : "r"(addr))

#define MMA16816(d, a0,a1,a2,a3, b0,b1) \
    asm volatile("mma.sync.aligned.m16n8k16.row.col.f32.f16.f16.f32 " \
        "{%0,%1,%2,%3}, {%4,%5,%6,%7}, {%8,%9}, {%0,%1,%2,%3};" \
        : "+f"(d[0]), "+f"(d[1]), "+f"(d[2]), "+f"(d[3]) \
        : "r"(a0), "r"(a1), "r"(a2), "r"(a3), "r"(b0), "r"(b1))

#define PAIR_BAR(id) asm volatile("bar.sync %0, 64;" :: "r"(id) : "memory")

// ---------------- weight pre-conversion (once per layer) ----------------
__global__ void k_wconv(const float* __restrict__ ew2, const float* __restrict__ cw1) {
    int l = blockIdx.x;
    int tid = threadIdx.x;
    const float* w2g = ew2 + (size_t)l * 4096;
    const float* c1g = cw1 + (size_t)l * 4096;
    for (int e = tid; e < 4096; e += 256) {
        int r = e >> 6, c = e & 63;
        g_W2h[l][r * 72 + c] = __float2half_rn(w2g[e]);
        g_C1h[l][r * 72 + c] = __float2half_rn(c1g[e]);
    }
}

// ---------------- init: x0, coord, embedding, layer-0 H1A/H1B, E0 ----------------
__global__ void k_init(const float* __restrict__ t, const float* __restrict__ x,
                       const float* __restrict__ at, const float* __restrict__ aat,
                       const float* __restrict__ aap, const float* __restrict__ nm,
                       const float* __restrict__ emb_w, const float* __restrict__ emb_b,
                       const float* __restrict__ ew1, const float* __restrict__ eb1) {
    int bn = blockIdx.x;
    int b = bn >> 8, i = bn & 255;
    int tid = threadIdx.x;                   // 256 threads
    __shared__ float sh[HD];
    float nmv = nm[bn];
    float xi0 = x[b * 768 + i * 3 + 0] * nmv;
    float xi1 = x[b * 768 + i * 3 + 1] * nmv;
    float xi2 = x[b * 768 + i * 3 + 2] * nmv;
    if (tid < 3) {
        float v = x[b * 768 + i * 3 + tid] * nmv;
        g_x0[bn * 3 + tid] = v;
        g_coordA[bn * 3 + tid] = v;
    }
    {
        float nmj = nm[b * 256 + tid];
        float dx = xi0 - x[b * 768 + tid * 3 + 0] * nmj;
        float dy = xi1 - x[b * 768 + tid * 3 + 1] * nmj;
        float dz = xi2 - x[b * 768 + tid * 3 + 2] * nmj;
        g_E0[bn * 256 + tid] = dx * dx + dy * dy + dz * dz;
    }
    if (tid < 64) {
        float f0 = at[bn] * nmv, f1 = aat[bn] * nmv, f2 = aap[bn] * nmv, f3 = t[b] * nmv;
        float h = emb_b[tid] + emb_w[tid * 4 + 0] * f0 + emb_w[tid * 4 + 1] * f1
                + emb_w[tid * 4 + 2] * f2 + emb_w[tid * 4 + 3] * f3;
        g_h[bn * HD + tid] = h;
        sh[tid] = h;
    }
    __syncthreads();
    int k = tid >> 2, q = tid & 3;
    const float* w1 = ew1 + (size_t)k * 130 + q * 16;     // layer 0
    const float* hp = sh + q * 16;
    float a = 0.f, bv = 0.f;
#pragma unroll
    for (int c = 0; c < 16; c++) { a += w1[c] * hp[c]; bv += w1[64 + c] * hp[c]; }
    a  += __shfl_xor_sync(0xffffffffu, a, 1);
    a  += __shfl_xor_sync(0xffffffffu, a, 2);
    bv += __shfl_xor_sync(0xffffffffu, bv, 1);
    bv += __shfl_xor_sync(0xffffffffu, bv, 2);
    if (q == 0) {
        g_H1A[bn * 64 + k] = a + eb1[k];
        g_H1Bh[0][bn * 64 + k] = __float2half_rn(bv);
    }
}

// ---------------- edge kernel smem layout ----------------
// fp16 tiles (half indices), stride 72 halfs
#define H_W2   0
#define H_C1   4608
#define H_MS   9216
#define H_M2   13824
// fp32 region (float indices); halves occupy floats [0, 9216)
#define S_COORD 9216
#define S_RADE  9984
#define S_DIFFN 10496
#define S_H1A   11264
#define S_WR    11328
#define S_WE    11392
#define S_B2    11456
#define S_CB1   11520
#define S_AW    11584
#define S_CW2   11648
#define S_ATTP  11712
#define S_PHIP  11840
#define S_CA0   11968
#define S_CA1   12032
#define S_CA2   12096
#define S_AGGP  12160
#define S_UPD   12416
#define SMEM_FLOATS 12672
#define SMEM_BYTES  (SMEM_FLOATS * 4)

__global__ void __launch_bounds__(256, 2)
k_edge(int l,
       const float* __restrict__ ew1, const float* __restrict__ eb1,
       const float* __restrict__ ew2, const float* __restrict__ eb2,
       const float* __restrict__ nw1, const float* __restrict__ nb1,
       const float* __restrict__ nw2, const float* __restrict__ nb2,
       const float* __restrict__ cw1, const float* __restrict__ cb1,
       const float* __restrict__ aw,  const float* __restrict__ ab,
       const float* __restrict__ cw2, const float* __restrict__ nm) {
    extern __shared__ float sm[];
    __half* smh = (__half*)sm;
    int ping = l & 1;
    const float* cIn = ping ? g_coordB : g_coordA;
    float* cOut = ping ? g_coordA : g_coordB;
    const __half* h1bIn = g_H1Bh[ping];
    __half* h1bOut = g_H1Bh[ping ^ 1];

    int tid = threadIdx.x;
    int wid = tid >> 5, lane = tid & 31;
    int t4 = lane >> 2, tq = lane & 3;
    int rh = lane >> 4, cc = lane & 15;     // agg lane remap
    int mrow = (wid & 3) << 4;
    int nhalf = (wid >> 2) << 5;
    int whalf = wid >> 2;
    int pairId = 1 + (wid & 3);
    int bn = blockIdx.x;
    int b = bn >> 8, i = bn & 255;

    // ---- stage weights (pre-converted fp16, uint4 copy) + vectors + coords ----
    {
        const uint4* sw2 = (const uint4*)(g_W2h[l]);
        const uint4* sc1 = (const uint4*)(g_C1h[l]);
        uint4* dw2 = (uint4*)(smh + H_W2);
        uint4* dc1 = (uint4*)(smh + H_C1);
        for (int e = tid; e < 576; e += 256) { dw2[e] = sw2[e]; dc1[e] = sc1[e]; }
    }
    if (tid < 64) {
        sm[S_WR  + tid] = ew1[((size_t)l * 64 + tid) * 130 + 128];
        sm[S_WE  + tid] = ew1[((size_t)l * 64 + tid) * 130 + 129];
        sm[S_B2  + tid] = eb2[l * 64 + tid];
        sm[S_CB1 + tid] = cb1[l * 64 + tid];
        sm[S_AW  + tid] = aw[l * 64 + tid];
        sm[S_CW2 + tid] = cw2[l * 64 + tid];
        sm[S_H1A + tid] = g_H1A[bn * 64 + tid];
        sm[S_CA0 + tid] = 0.f;
        sm[S_CA1 + tid] = 0.f;
        sm[S_CA2 + tid] = 0.f;
    }
    for (int e = tid; e < 768; e += 256) sm[S_COORD + e] = cIn[b * 768 + e];
    float attb = ab[l];
    float nmi = nm[bn];
    __syncthreads();

    // ---- geometry + (rad,e0) for ALL 256 j (once) ----
    {
        float cix = sm[S_COORD + i * 3], ciy = sm[S_COORD + i * 3 + 1], ciz = sm[S_COORD + i * 3 + 2];
        int j = tid;
        float dx = cix - sm[S_COORD + j * 3];
        float dy = ciy - sm[S_COORD + j * 3 + 1];
        float dz = ciz - sm[S_COORD + j * 3 + 2];
        float rad = dx * dx + dy * dy + dz * dz;
        float inv = 1.f / (sqrtf(rad + 1e-8f) + 1.f);
        float2 re; re.x = rad; re.y = __ldg(g_E0 + (size_t)bn * 256 + j);
        *(float2*)(sm + S_RADE + j * 2) = re;
        sm[S_DIFFN + j * 3 + 0] = dx * inv;
        sm[S_DIFFN + j * 3 + 1] = dy * inv;
        sm[S_DIFFN + j * 3 + 2] = dz * inv;
    }
    __syncthreads();

    // ---- ldmatrix lane addressing ----
    uint32_t sbase = (uint32_t)__cvta_generic_to_shared((void*)sm);
    int ar = (lane & 7) + ((lane >> 3) & 1) * 8;
    int ac = (lane >> 4) * 8;
    uint32_t aoff = (uint32_t)(((mrow + ar) * 72 + ac) * 2);
    int br = (lane & 7) + ((lane >> 4) ? 8 : 0);
    int bc = ((lane >> 3) & 1) * 8;
    uint32_t boff = (uint32_t)(((nhalf + br) * 72 + bc) * 2);
    uint32_t aMS = sbase + H_MS * 2 + aoff;
    uint32_t aM2 = sbase + H_M2 * 2 + aoff;
    uint32_t bW2 = sbase + H_W2 * 2 + boff;
    uint32_t bC1 = sbase + H_C1 * 2 + boff;

    // ---- hoist B fragments (tile-invariant) into registers ----
    uint32_t fw[4][2][4], fc[4][2][4];
#pragma unroll
    for (int kk = 0; kk < 4; kk++)
#pragma unroll
        for (int ntp = 0; ntp < 2; ntp++) {
            LDSM4(fw[kk][ntp][0], fw[kk][ntp][1], fw[kk][ntp][2], fw[kk][ntp][3],
                  bW2 + ntp * 2304 + kk * 32);
            LDSM4(fc[kk][ntp][0], fc[kk][ntp][1], fc[kk][ntp][2], fc[kk][ntp][3],
                  bC1 + ntp * 2304 + kk * 32);
        }

    float aggA = 0.f, aggB = 0.f;   // cols nhalf+2cc, +1; rows mrow+8rh..+7
    const float* nmb = nm + b * 256;
    int r0 = mrow + t4, r1 = r0 + 8;

    for (int tile = 0; tile < 4; tile++) {
        int j0 = tile << 6;
        // ---- phase F (finalize previous tile's phi/coord) + phase B ----
        if (tile > 0 && tid < 64) {
            int j = j0 - 64 + tid;
            float p = sm[S_PHIP + tid * 2] + sm[S_PHIP + tid * 2 + 1];
            float em = (j == i) ? 0.f : nmi * __ldg(nmb + j);
            float ph = tanhf(p) * CRANGE * em;
            sm[S_CA0 + tid] += sm[S_DIFFN + j * 3 + 0] * ph;
            sm[S_CA1 + tid] += sm[S_DIFFN + j * 3 + 1] * ph;
            sm[S_CA2 + tid] += sm[S_DIFFN + j * 3 + 2] * ph;
        }
        const __half* h1bg = h1bIn + ((size_t)(b * 256 + j0)) * 64;
#pragma unroll
        for (int it = 0; it < 4; it++) {
            int p = tid + it * 256;
            int jj = p >> 4, q4 = (p & 15) * 4;
            uint2 hraw = *(const uint2*)(h1bg + jj * 64 + q4);
            float2 hb01 = __half22float2(*(__half2*)&hraw.x);
            float2 hb23 = __half22float2(*(__half2*)&hraw.y);
            float2 re = *(const float2*)(sm + S_RADE + (j0 + jj) * 2);
            float v0 = silu_h(sm[S_H1A + q4]     + hb01.x + sm[S_WR + q4]     * re.x + sm[S_WE + q4]     * re.y);
            float v1 = silu_h(sm[S_H1A + q4 + 1] + hb01.y + sm[S_WR + q4 + 1] * re.x + sm[S_WE + q4 + 1] * re.y);
            float v2 = silu_h(sm[S_H1A + q4 + 2] + hb23.x + sm[S_WR + q4 + 2] * re.x + sm[S_WE + q4 + 2] * re.y);
            float v3 = silu_h(sm[S_H1A + q4 + 3] + hb23.y + sm[S_WR + q4 + 3] * re.x + sm[S_WE + q4 + 3] * re.y);
            __half2 ha = __floats2half2_rn(v0, v1);
            __half2 hb2 = __floats2half2_rn(v2, v3);
            uint2 u; u.x = *(uint32_t*)&ha; u.y = *(uint32_t*)&hb2;
            *(uint2*)(smh + H_MS + jj * 72 + q4) = u;       // single STS.64
        }
        __syncthreads();
        // ---- phase C: GEMM1 (HMMA, B from regs) + epilogue ----
        {
            float acc[4][4];
#pragma unroll
            for (int nt = 0; nt < 4; nt++)
#pragma unroll
                for (int r = 0; r < 4; r++) acc[nt][r] = 0.f;
#pragma unroll
            for (int kk = 0; kk < 4; kk++) {
                uint32_t a0, a1, a2, a3;
                LDSM4(a0, a1, a2, a3, aMS + kk * 32);
#pragma unroll
                for (int ntp = 0; ntp < 2; ntp++) {
                    MMA16816(acc[2 * ntp],     a0, a1, a2, a3, fw[kk][ntp][0], fw[kk][ntp][1]);
                    MMA16816(acc[2 * ntp + 1], a0, a1, a2, a3, fw[kk][ntp][2], fw[kk][ntp][3]);
                }
            }
            float ap0 = 0.f, ap1 = 0.f;
#pragma unroll
            for (int nt = 0; nt < 4; nt++) {
                int c0 = nhalf + nt * 8 + 2 * tq;
                float b2a = sm[S_B2 + c0], b2b = sm[S_B2 + c0 + 1];
                float m00 = silu_h(acc[nt][0] + b2a);
                float m01 = silu_h(acc[nt][1] + b2b);
                float m10 = silu_h(acc[nt][2] + b2a);
                float m11 = silu_h(acc[nt][3] + b2b);
                *(__half2*)(smh + H_M2 + r0 * 72 + c0) = __floats2half2_rn(m00, m01);
                *(__half2*)(smh + H_M2 + r1 * 72 + c0) = __floats2half2_rn(m10, m11);
                float awa = sm[S_AW + c0], awb = sm[S_AW + c0 + 1];
                ap0 += m00 * awa + m01 * awb;
                ap1 += m10 * awa + m11 * awb;
            }
            ap0 += __shfl_xor_sync(0xffffffffu, ap0, 1);
            ap0 += __shfl_xor_sync(0xffffffffu, ap0, 2);
            ap1 += __shfl_xor_sync(0xffffffffu, ap1, 1);
            ap1 += __shfl_xor_sync(0xffffffffu, ap1, 2);
            if (tq == 0) {
                sm[S_ATTP + r0 * 2 + whalf] = ap0;
                sm[S_ATTP + r1 * 2 + whalf] = ap1;
            }
        }
        PAIR_BAR(pairId);   // phase E only touches pair-local M2/ATTP
        // ---- phase E: atts in-warp, GEMM2 (HMMA, B from regs), phi, agg ----
        {
            float attsOwn = 0.f;
            if (lane < 16) {
                int r = mrow + lane;
                int j = j0 + r;
                float dot = sm[S_ATTP + r * 2] + sm[S_ATTP + r * 2 + 1] + attb;
                float em = (j == i) ? 0.f : nmi * __ldg(nmb + j);
                attsOwn = sigm_h(dot) * em;
            }
            float sr0 = __shfl_sync(0xffffffffu, attsOwn, t4);
            float sr1 = __shfl_sync(0xffffffffu, attsOwn, t4 + 8);

            float acc[4][4];
#pragma unroll
            for (int nt = 0; nt < 4; nt++)
#pragma unroll
                for (int r = 0; r < 4; r++) acc[nt][r] = 0.f;
#pragma unroll
            for (int kk = 0; kk < 4; kk++) {
                uint32_t a0, a1, a2, a3;
                LDSM4(a0, a1, a2, a3, aM2 + kk * 32);
#pragma unroll
                for (int ntp = 0; ntp < 2; ntp++) {
                    MMA16816(acc[2 * ntp],     a0, a1, a2, a3, fc[kk][ntp][0], fc[kk][ntp][1]);
                    MMA16816(acc[2 * ntp + 1], a0, a1, a2, a3, fc[kk][ntp][2], fc[kk][ntp][3]);
                }
            }
            float pp0 = 0.f, pp1 = 0.f;
#pragma unroll
            for (int nt = 0; nt < 4; nt++) {
                int c0 = nhalf + nt * 8 + 2 * tq;
                float cba = sm[S_CB1 + c0], cbb = sm[S_CB1 + c0 + 1];
                float cwa = sm[S_CW2 + c0], cwb = sm[S_CW2 + c0 + 1];
                pp0 += silu_h(fmaf(sr0, acc[nt][0], cba)) * cwa
                     + silu_h(fmaf(sr0, acc[nt][1], cbb)) * cwb;
                pp1 += silu_h(fmaf(sr1, acc[nt][2], cba)) * cwa
                     + silu_h(fmaf(sr1, acc[nt][3], cbb)) * cwb;
            }
            pp0 += __shfl_xor_sync(0xffffffffu, pp0, 1);
            pp0 += __shfl_xor_sync(0xffffffffu, pp0, 2);
            pp1 += __shfl_xor_sync(0xffffffffu, pp1, 1);
            pp1 += __shfl_xor_sync(0xffffffffu, pp1, 2);
            if (tq == 0) {
                sm[S_PHIP + r0 * 2 + whalf] = pp0;
                sm[S_PHIP + r1 * 2 + whalf] = pp1;
            }
            // agg: half2 loads — lane = 16*rh + cc handles cols (nhalf+2cc,+1), 8 rows
            const __half2* pm2 = (const __half2*)(smh + H_M2 + (mrow + 8 * rh) * 72 + nhalf + 2 * cc);
#pragma unroll
            for (int jj = 0; jj < 8; jj++) {
                float aj = __shfl_sync(0xffffffffu, attsOwn, 8 * rh + jj);
                float2 mv = __half22float2(pm2[jj * 36]);
                aggA += mv.x * aj;
                aggB += mv.y * aj;
            }
        }
        __syncthreads();
    }
    // ---- tail: finalize tile-3 phi/coord, agg store, coord out, node update ----
    if (tid < 64) {
        int j = 192 + tid;
        float p = sm[S_PHIP + tid * 2] + sm[S_PHIP + tid * 2 + 1];
        float em = (j == i) ? 0.f : nmi * __ldg(nmb + j);
        float ph = tanhf(p) * CRANGE * em;
        sm[S_CA0 + tid] += sm[S_DIFFN + j * 3 + 0] * ph;
        sm[S_CA1 + tid] += sm[S_DIFFN + j * 3 + 1] * ph;
        sm[S_CA2 + tid] += sm[S_DIFFN + j * 3 + 2] * ph;
    }
    aggA += __shfl_xor_sync(0xffffffffu, aggA, 16);
    aggB += __shfl_xor_sync(0xffffffffu, aggB, 16);
    if (lane < 16) {
        float2 v; v.x = aggA; v.y = aggB;
        *(float2*)(sm + S_AGGP + (wid & 3) * 64 + nhalf + 2 * lane) = v;
    }
    __syncthreads();
    if (tid < 64) {
        sm[S_UPD + tid] = g_h[bn * 64 + tid];
        sm[S_UPD + 64 + tid] = sm[S_AGGP + tid] + sm[S_AGGP + 64 + tid]
                             + sm[S_AGGP + 128 + tid] + sm[S_AGGP + 192 + tid];
    }
    __syncthreads();
    if (tid < 3) {
        float s = 0.f;
#pragma unroll
        for (int q = 0; q < 64; q++) s += sm[S_CA0 + tid * 64 + q];
        cOut[bn * 3 + tid] = (sm[S_COORD + i * 3 + tid] + s) * nmi;
    }
    if (l < NL - 1) {
        int k = tid >> 2, q = tid & 3;
        {
            const float* w1 = nw1 + ((size_t)l * 64 + k) * 128 + q * 32;
            const float* src = sm + S_UPD + q * 32;
            float acc = 0.f;
#pragma unroll
            for (int c = 0; c < 32; c++) acc += w1[c] * src[c];
            acc += __shfl_xor_sync(0xffffffffu, acc, 1);
            acc += __shfl_xor_sync(0xffffffffu, acc, 2);
            if (q == 0) sm[S_UPD + 128 + k] = siluf(acc + nb1[l * 64 + k]);
        }
        __syncthreads();
        {
            const float* w2 = nw2 + ((size_t)l * 64 + k) * 64 + q * 16;
            const float* stp = sm + S_UPD + 128 + q * 16;
            float u = 0.f;
#pragma unroll
            for (int c = 0; c < 16; c++) u += w2[c] * stp[c];
            u += __shfl_xor_sync(0xffffffffu, u, 1);
            u += __shfl_xor_sync(0xffffffffu, u, 2);
            if (q == 0) {
                float hn = (sm[S_UPD + k] + u + nb2[l * 64 + k]) * nmi;
                sm[S_UPD + 192 + k] = hn;
                g_h[bn * 64 + k] = hn;
            }
        }
        __syncthreads();
        {
            const float* w1n = ew1 + ((size_t)(l + 1) * 64 + k) * 130 + q * 16;
            const float* hp = sm + S_UPD + 192 + q * 16;
            float a = 0.f, bv = 0.f;
#pragma unroll
            for (int c = 0; c < 16; c++) { a += w1n[c] * hp[c]; bv += w1n[64 + c] * hp[c]; }
            a  += __shfl_xor_sync(0xffffffffu, a, 1);
            a  += __shfl_xor_sync(0xffffffffu, a, 2);
            bv += __shfl_xor_sync(0xffffffffu, bv, 1);
            bv += __shfl_xor_sync(0xffffffffu, bv, 2);
            if (q == 0) {
                g_H1A[bn * 64 + k] = a + eb1[(l + 1) * 64 + k];
                h1bOut[bn * 64 + k] = __float2half_rn(bv);
            }
        }
    }
}

// ---------------- final: vel + remove mean ----------------
__global__ void k_final(const float* __restrict__ nm, float* __restrict__ out) {
    int b = blockIdx.x;
    int j = threadIdx.x;                     // 256 threads
    __shared__ float rs[256 * 4];
    int bn = b * 256 + j;
    float nmv = nm[bn];
    float v0 = (g_coordA[bn * 3 + 0] - g_x0[bn * 3 + 0]) * nmv;
    float v1 = (g_coordA[bn * 3 + 1] - g_x0[bn * 3 + 1]) * nmv;
    float v2 = (g_coordA[bn * 3 + 2] - g_x0[bn * 3 + 2]) * nmv;
    rs[j] = v0; rs[256 + j] = v1; rs[512 + j] = v2; rs[768 + j] = nmv;
    __syncthreads();
    for (int o = 128; o > 0; o >>= 1) {
        if (j < o) {
            rs[j] += rs[j + o];
            rs[256 + j] += rs[256 + j + o];
            rs[512 + j] += rs[512 + j + o];
            rs[768 + j] += rs[768 + j + o];
        }
        __syncthreads();
    }
    float inv = 1.f / rs[768];
    float m0 = rs[0] * inv, m1 = rs[256] * inv, m2 = rs[512] * inv;
    out[b * 768 + j * 3 + 0] = v0 - m0 * nmv;
    out[b * 768 + j * 3 + 1] = v1 - m1 * nmv;
    out[b * 768 + j * 3 + 2] = v2 - m2 * nmv;
}

// ---------------- launch ----------------
extern "C" void kernel_launch(void* const* d_in, const int* in_sizes, int n_in,
                              void* d_out, int out_size) {
    (void)in_sizes; (void)n_in; (void)out_size;
    const float* t     = (const float*)d_in[0];
    const float* x     = (const float*)d_in[1];
    const float* at    = (const float*)d_in[2];
    const float* aat   = (const float*)d_in[3];
    const float* aap   = (const float*)d_in[4];
    const float* nm    = (const float*)d_in[5];
    const float* emb_w = (const float*)d_in[6];
    const float* emb_b = (const float*)d_in[7];
    const float* ew1   = (const float*)d_in[8];
    const float* eb1   = (const float*)d_in[9];
    const float* ew2   = (const float*)d_in[10];
    const float* eb2   = (const float*)d_in[11];
    const float* nw1   = (const float*)d_in[12];
    const float* nb1   = (const float*)d_in[13];
    const float* nw2   = (const float*)d_in[14];
    const float* nb2   = (const float*)d_in[15];
    const float* cw1   = (const float*)d_in[16];
    const float* cb1   = (const float*)d_in[17];
    const float* aw    = (const float*)d_in[18];
    const float* ab    = (const float*)d_in[19];
    const float* cw2   = (const float*)d_in[20];
    float* out = (float*)d_out;

    cudaFuncSetAttribute(k_edge, cudaFuncAttributeMaxDynamicSharedMemorySize, SMEM_BYTES);

    k_wconv<<<NL, 256>>>(ew2, cw1);
    k_init<<<BN, 256>>>(t, x, at, aat, aap, nm, emb_w, emb_b, ew1, eb1);
    for (int l = 0; l < NL; l++) {
        k_edge<<<BN, 256, SMEM_BYTES>>>(l, ew1, eb1, ew2, eb2,
                                        nw1, nb1, nw2, nb2, cw1, cb1, aw, ab, cw2, nm);
    }
    k_final<<<NB, 256>>>(nm, out);
}

// round 16
// speedup vs baseline: 1.0004x; 1.0004x over previous
#include <cuda_runtime.h>
#include <cuda_fp16.h>
#include <cstdint>

#define NB 8
#define NN 256
#define BN (NB*NN)          // 2048 nodes
#define HD 64
#define NL 4
#define CRANGE 3.75f        // 15.0 / 4 layers

// ---------------- device scratch ----------------
__device__ __align__(16) float g_h[BN*HD];
__device__ __align__(16) float g_H1A[BN*HD];
__device__ __align__(16) __half g_H1Bh[2][BN*HD];
__device__ __align__(16) float g_E0[BN*NN];
__device__ __align__(16) float g_coordA[BN*3];
__device__ __align__(16) float g_coordB[BN*3];
__device__ __align__(16) float g_x0[BN*3];
__device__ __align__(16) __half g_W2h[NL][64*72];
__device__ __align__(16) __half g_C1h[NL][64*72];

__device__ __forceinline__ float tanh_ap(float x) {
    float y; asm("tanh.approx.f32 %0, %1;" : "=f"(y) : "f"(x)); return y;
}
__device__ __forceinline__ float silu_h(float x) {
    return x * fmaf(0.5f, tanh_ap(0.5f * x), 0.5f);
}
__device__ __forceinline__ float sigm_h(float x) {
    return fmaf(0.5f, tanh_ap(0.5f * x), 0.5f);
}
__device__ __forceinline__ float siluf(float x) {
    return __fdividef(x, 1.f + __expf(-x));
}

// ---------------- HMMA helpers ----------------
#define LDSM4(r0,r1,r2,r3, addr) \
    asm volatile("ldmatrix.sync.aligned.m8n8.x4.shared.b16 {%0,%1,%2,%3}, [%4];" \
        : "=r"(r0), "=r"(r1), "=r"(r2), "=r"(r3) : "r"(addr))

#define MMA16816(d, a0,a1,a2,a3, b0,b1) \
    asm volatile("mma.sync.aligned.m16n8k16.row.col.f32.f16.f16.f32 " \
        "{%0,%1,%2,%3}, {%4,%5,%6,%7}, {%8,%9}, {%0,%1,%2,%3};" \
        : "+f"(d[0]), "+f"(d[1]), "+f"(d[2]), "+f"(d[3]) \
        : "r"(a0), "r"(a1), "r"(a2), "r"(a3), "r"(b0), "r"(b1))

#define PAIR_BAR(id) asm volatile("bar.sync %0, 64;" :: "r"(id) : "memory")

// ---------------- weight pre-conversion (once per layer) ----------------
__global__ void k_wconv(const float* __restrict__ ew2, const float* __restrict__ cw1) {
    int l = blockIdx.x;
    int tid = threadIdx.x;
    const float* w2g = ew2 + (size_t)l * 4096;
    const float* c1g = cw1 + (size_t)l * 4096;
    for (int e = tid; e < 4096; e += 256) {
        int r = e >> 6, c = e & 63;
        g_W2h[l][r * 72 + c] = __float2half_rn(w2g[e]);
        g_C1h[l][r * 72 + c] = __float2half_rn(c1g[e]);
    }
}

// ---------------- init: x0, coord, embedding, layer-0 H1A/H1B, E0 ----------------
__global__ void k_init(const float* __restrict__ t, const float* __restrict__ x,
                       const float* __restrict__ at, const float* __restrict__ aat,
                       const float* __restrict__ aap, const float* __restrict__ nm,
                       const float* __restrict__ emb_w, const float* __restrict__ emb_b,
                       const float* __restrict__ ew1, const float* __restrict__ eb1) {
    int bn = blockIdx.x;
    int b = bn >> 8, i = bn & 255;
    int tid = threadIdx.x;                   // 256 threads
    __shared__ float sh[HD];
    float nmv = nm[bn];
    float xi0 = x[b * 768 + i * 3 + 0] * nmv;
    float xi1 = x[b * 768 + i * 3 + 1] * nmv;
    float xi2 = x[b * 768 + i * 3 + 2] * nmv;
    if (tid < 3) {
        float v = x[b * 768 + i * 3 + tid] * nmv;
        g_x0[bn * 3 + tid] = v;
        g_coordA[bn * 3 + tid] = v;
    }
    {
        float nmj = nm[b * 256 + tid];
        float dx = xi0 - x[b * 768 + tid * 3 + 0] * nmj;
        float dy = xi1 - x[b * 768 + tid * 3 + 1] * nmj;
        float dz = xi2 - x[b * 768 + tid * 3 + 2] * nmj;
        g_E0[bn * 256 + tid] = dx * dx + dy * dy + dz * dz;
    }
    if (tid < 64) {
        float f0 = at[bn] * nmv, f1 = aat[bn] * nmv, f2 = aap[bn] * nmv, f3 = t[b] * nmv;
        float h = emb_b[tid] + emb_w[tid * 4 + 0] * f0 + emb_w[tid * 4 + 1] * f1
                + emb_w[tid * 4 + 2] * f2 + emb_w[tid * 4 + 3] * f3;
        g_h[bn * HD + tid] = h;
        sh[tid] = h;
    }
    __syncthreads();
    int k = tid >> 2, q = tid & 3;
    const float* w1 = ew1 + (size_t)k * 130 + q * 16;     // layer 0
    const float* hp = sh + q * 16;
    float a = 0.f, bv = 0.f;
#pragma unroll
    for (int c = 0; c < 16; c++) { a += w1[c] * hp[c]; bv += w1[64 + c] * hp[c]; }
    a  += __shfl_xor_sync(0xffffffffu, a, 1);
    a  += __shfl_xor_sync(0xffffffffu, a, 2);
    bv += __shfl_xor_sync(0xffffffffu, bv, 1);
    bv += __shfl_xor_sync(0xffffffffu, bv, 2);
    if (q == 0) {
        g_H1A[bn * 64 + k] = a + eb1[k];
        g_H1Bh[0][bn * 64 + k] = __float2half_rn(bv);
    }
}

// ---------------- edge kernel smem layout ----------------
// fp16 tiles (half indices), stride 72 halfs; MS double-buffered
#define H_W2   0
#define H_C1   4608
#define H_MS0  9216
#define H_MS1  18432
#define H_M2   27648
// fp32 region (float indices); halves occupy floats [0, 16128)
#define S_COORD 16128
#define S_RADE  16896
#define S_DIFFN 17408
#define S_H1A   18176
#define S_WR    18240
#define S_WE    18304
#define S_B2    18368
#define S_CB1   18432
#define S_AW    18496
#define S_CW2   18560
#define S_ATTP  18624
#define S_PHIP  18752     // 256 floats: double-buffered (128 per buf)
#define S_CA0   19008
#define S_CA1   19072
#define S_CA2   19136
#define S_AGGP  19200
#define S_UPD   19456
#define SMEM_FLOATS 19712
#define SMEM_BYTES  (SMEM_FLOATS * 4)

__global__ void __launch_bounds__(256, 2)
k_edge(int l,
       const float* __restrict__ ew1, const float* __restrict__ eb1,
       const float* __restrict__ ew2, const float* __restrict__ eb2,
       const float* __restrict__ nw1, const float* __restrict__ nb1,
       const float* __restrict__ nw2, const float* __restrict__ nb2,
       const float* __restrict__ cw1, const float* __restrict__ cb1,
       const float* __restrict__ aw,  const float* __restrict__ ab,
       const float* __restrict__ cw2, const float* __restrict__ nm) {
    extern __shared__ float sm[];
    __half* smh = (__half*)sm;
    int ping = l & 1;
    const float* cIn = ping ? g_coordB : g_coordA;
    float* cOut = ping ? g_coordA : g_coordB;
    const __half* h1bIn = g_H1Bh[ping];
    __half* h1bOut = g_H1Bh[ping ^ 1];

    int tid = threadIdx.x;
    int wid = tid >> 5, lane = tid & 31;
    int t4 = lane >> 2, tq = lane & 3;
    int rh = lane >> 4, cc = lane & 15;     // agg lane remap
    int mrow = (wid & 3) << 4;
    int nhalf = (wid >> 2) << 5;
    int whalf = wid >> 2;
    int pairId = 1 + (wid & 3);
    int bn = blockIdx.x;
    int b = bn >> 8, i = bn & 255;

    // ---- stage weights (pre-converted fp16, uint4 copy) + vectors + coords ----
    {
        const uint4* sw2 = (const uint4*)(g_W2h[l]);
        const uint4* sc1 = (const uint4*)(g_C1h[l]);
        uint4* dw2 = (uint4*)(smh + H_W2);
        uint4* dc1 = (uint4*)(smh + H_C1);
        for (int e = tid; e < 576; e += 256) { dw2[e] = sw2[e]; dc1[e] = sc1[e]; }
    }
    if (tid < 64) {
        sm[S_WR  + tid] = ew1[((size_t)l * 64 + tid) * 130 + 128];
        sm[S_WE  + tid] = ew1[((size_t)l * 64 + tid) * 130 + 129];
        sm[S_B2  + tid] = eb2[l * 64 + tid];
        sm[S_CB1 + tid] = cb1[l * 64 + tid];
        sm[S_AW  + tid] = aw[l * 64 + tid];
        sm[S_CW2 + tid] = cw2[l * 64 + tid];
        sm[S_H1A + tid] = g_H1A[bn * 64 + tid];
        sm[S_CA0 + tid] = 0.f;
        sm[S_CA1 + tid] = 0.f;
        sm[S_CA2 + tid] = 0.f;
    }
    for (int e = tid; e < 768; e += 256) sm[S_COORD + e] = cIn[b * 768 + e];
    float attb = ab[l];
    float nmi = nm[bn];
    __syncthreads();

    // ---- geometry + (rad,e0) for ALL 256 j (once) ----
    {
        float cix = sm[S_COORD + i * 3], ciy = sm[S_COORD + i * 3 + 1], ciz = sm[S_COORD + i * 3 + 2];
        int j = tid;
        float dx = cix - sm[S_COORD + j * 3];
        float dy = ciy - sm[S_COORD + j * 3 + 1];
        float dz = ciz - sm[S_COORD + j * 3 + 2];
        float rad = dx * dx + dy * dy + dz * dz;
        float inv = 1.f / (sqrtf(rad + 1e-8f) + 1.f);
        float2 re; re.x = rad; re.y = __ldg(g_E0 + (size_t)bn * 256 + j);
        *(float2*)(sm + S_RADE + j * 2) = re;
        sm[S_DIFFN + j * 3 + 0] = dx * inv;
        sm[S_DIFFN + j * 3 + 1] = dy * inv;
        sm[S_DIFFN + j * 3 + 2] = dz * inv;
    }
    __syncthreads();

    // ---- ldmatrix lane addressing ----
    uint32_t sbase = (uint32_t)__cvta_generic_to_shared((void*)sm);
    int ar = (lane & 7) + ((lane >> 3) & 1) * 8;
    int ac = (lane >> 4) * 8;
    uint32_t aoff = (uint32_t)(((mrow + ar) * 72 + ac) * 2);
    int br = (lane & 7) + ((lane >> 4) ? 8 : 0);
    int bc = ((lane >> 3) & 1) * 8;
    uint32_t boff = (uint32_t)(((nhalf + br) * 72 + bc) * 2);
    uint32_t aMS0 = sbase + H_MS0 * 2 + aoff;
    uint32_t aM2 = sbase + H_M2 * 2 + aoff;
    uint32_t bW2 = sbase + H_W2 * 2 + boff;
    uint32_t bC1 = sbase + H_C1 * 2 + boff;

    // ---- hoist B fragments (tile-invariant) into registers ----
    uint32_t fw[4][2][4], fc[4][2][4];
#pragma unroll
    for (int kk = 0; kk < 4; kk++)
#pragma unroll
        for (int ntp = 0; ntp < 2; ntp++) {
            LDSM4(fw[kk][ntp][0], fw[kk][ntp][1], fw[kk][ntp][2], fw[kk][ntp][3],
                  bW2 + ntp * 2304 + kk * 32);
            LDSM4(fc[kk][ntp][0], fc[kk][ntp][1], fc[kk][ntp][2], fc[kk][ntp][3],
                  bC1 + ntp * 2304 + kk * 32);
        }

    float aggA = 0.f, aggB = 0.f;   // cols nhalf+2cc, +1; rows mrow+8rh..+7
    const float* nmb = nm + b * 256;
    int r0 = mrow + t4, r1 = r0 + 8;

    for (int tile = 0; tile < 4; tile++) {
        int j0 = tile << 6;
        int buf = tile & 1;
        // ---- phase B: Mpre + silu -> MS[buf] (all threads) ----
        const __half* h1bg = h1bIn + ((size_t)(b * 256 + j0)) * 64;
        __half* msb = smh + (buf ? H_MS1 : H_MS0);
#pragma unroll
        for (int it = 0; it < 4; it++) {
            int p = tid + it * 256;
            int jj = p >> 4, q4 = (p & 15) * 4;
            uint2 hraw = *(const uint2*)(h1bg + jj * 64 + q4);
            float2 hb01 = __half22float2(*(__half2*)&hraw.x);
            float2 hb23 = __half22float2(*(__half2*)&hraw.y);
            float2 re = *(const float2*)(sm + S_RADE + (j0 + jj) * 2);
            float v0 = silu_h(sm[S_H1A + q4]     + hb01.x + sm[S_WR + q4]     * re.x + sm[S_WE + q4]     * re.y);
            float v1 = silu_h(sm[S_H1A + q4 + 1] + hb01.y + sm[S_WR + q4 + 1] * re.x + sm[S_WE + q4 + 1] * re.y);
            float v2 = silu_h(sm[S_H1A + q4 + 2] + hb23.x + sm[S_WR + q4 + 2] * re.x + sm[S_WE + q4 + 2] * re.y);
            float v3 = silu_h(sm[S_H1A + q4 + 3] + hb23.y + sm[S_WR + q4 + 3] * re.x + sm[S_WE + q4 + 3] * re.y);
            __half2 ha = __floats2half2_rn(v0, v1);
            __half2 hb2 = __floats2half2_rn(v2, v3);
            uint2 u; u.x = *(uint32_t*)&ha; u.y = *(uint32_t*)&hb2;
            *(uint2*)(msb + jj * 72 + q4) = u;
        }
        __syncthreads();   // the ONLY full barrier per tile
        // ---- phase F: finalize previous tile's phi/coord (reads PHIP[buf^1]) ----
        if (tile > 0 && tid < 64) {
            int j = j0 - 64 + tid;
            const float* php = sm + S_PHIP + (buf ^ 1) * 128;
            float p = php[tid * 2] + php[tid * 2 + 1];
            float em = (j == i) ? 0.f : nmi * __ldg(nmb + j);
            float ph = tanhf(p) * CRANGE * em;
            sm[S_CA0 + tid] += sm[S_DIFFN + j * 3 + 0] * ph;
            sm[S_CA1 + tid] += sm[S_DIFFN + j * 3 + 1] * ph;
            sm[S_CA2 + tid] += sm[S_DIFFN + j * 3 + 2] * ph;
        }
        // ---- phase C: GEMM1 (HMMA, B from regs) + epilogue ----
        {
            uint32_t aMS = aMS0 + (uint32_t)(buf * (9216 * 2));
            float acc[4][4];
#pragma unroll
            for (int nt = 0; nt < 4; nt++)
#pragma unroll
                for (int r = 0; r < 4; r++) acc[nt][r] = 0.f;
#pragma unroll
            for (int kk = 0; kk < 4; kk++) {
                uint32_t a0, a1, a2, a3;
                LDSM4(a0, a1, a2, a3, aMS + kk * 32);
#pragma unroll
                for (int ntp = 0; ntp < 2; ntp++) {
                    MMA16816(acc[2 * ntp],     a0, a1, a2, a3, fw[kk][ntp][0], fw[kk][ntp][1]);
                    MMA16816(acc[2 * ntp + 1], a0, a1, a2, a3, fw[kk][ntp][2], fw[kk][ntp][3]);
                }
            }
            float ap0 = 0.f, ap1 = 0.f;
#pragma unroll
            for (int nt = 0; nt < 4; nt++) {
                int c0 = nhalf + nt * 8 + 2 * tq;
                float b2a = sm[S_B2 + c0], b2b = sm[S_B2 + c0 + 1];
                float m00 = silu_h(acc[nt][0] + b2a);
                float m01 = silu_h(acc[nt][1] + b2b);
                float m10 = silu_h(acc[nt][2] + b2a);
                float m11 = silu_h(acc[nt][3] + b2b);
                *(__half2*)(smh + H_M2 + r0 * 72 + c0) = __floats2half2_rn(m00, m01);
                *(__half2*)(smh + H_M2 + r1 * 72 + c0) = __floats2half2_rn(m10, m11);
                float awa = sm[S_AW + c0], awb = sm[S_AW + c0 + 1];
                ap0 += m00 * awa + m01 * awb;
                ap1 += m10 * awa + m11 * awb;
            }
            ap0 += __shfl_xor_sync(0xffffffffu, ap0, 1);
            ap0 += __shfl_xor_sync(0xffffffffu, ap0, 2);
            ap1 += __shfl_xor_sync(0xffffffffu, ap1, 1);
            ap1 += __shfl_xor_sync(0xffffffffu, ap1, 2);
            if (tq == 0) {
                sm[S_ATTP + r0 * 2 + whalf] = ap0;
                sm[S_ATTP + r1 * 2 + whalf] = ap1;
            }
        }
        PAIR_BAR(pairId);   // phase E touches only pair-local M2/ATTP
        // ---- phase E: atts in-warp, GEMM2 (HMMA, B from regs), phi, agg ----
        {
            float attsOwn = 0.f;
            if (lane < 16) {
                int r = mrow + lane;
                int j = j0 + r;
                float dot = sm[S_ATTP + r * 2] + sm[S_ATTP + r * 2 + 1] + attb;
                float em = (j == i) ? 0.f : nmi * __ldg(nmb + j);
                attsOwn = sigm_h(dot) * em;
            }
            float sr0 = __shfl_sync(0xffffffffu, attsOwn, t4);
            float sr1 = __shfl_sync(0xffffffffu, attsOwn, t4 + 8);

            float acc[4][4];
#pragma unroll
            for (int nt = 0; nt < 4; nt++)
#pragma unroll
                for (int r = 0; r < 4; r++) acc[nt][r] = 0.f;
#pragma unroll
            for (int kk = 0; kk < 4; kk++) {
                uint32_t a0, a1, a2, a3;
                LDSM4(a0, a1, a2, a3, aM2 + kk * 32);
#pragma unroll
                for (int ntp = 0; ntp < 2; ntp++) {
                    MMA16816(acc[2 * ntp],     a0, a1, a2, a3, fc[kk][ntp][0], fc[kk][ntp][1]);
                    MMA16816(acc[2 * ntp + 1], a0, a1, a2, a3, fc[kk][ntp][2], fc[kk][ntp][3]);
                }
            }
            float pp0 = 0.f, pp1 = 0.f;
#pragma unroll
            for (int nt = 0; nt < 4; nt++) {
                int c0 = nhalf + nt * 8 + 2 * tq;
                float cba = sm[S_CB1 + c0], cbb = sm[S_CB1 + c0 + 1];
                float cwa = sm[S_CW2 + c0], cwb = sm[S_CW2 + c0 + 1];
                pp0 += silu_h(fmaf(sr0, acc[nt][0], cba)) * cwa
                     + silu_h(fmaf(sr0, acc[nt][1], cbb)) * cwb;
                pp1 += silu_h(fmaf(sr1, acc[nt][2], cba)) * cwa
                     + silu_h(fmaf(sr1, acc[nt][3], cbb)) * cwb;
            }
            pp0 += __shfl_xor_sync(0xffffffffu, pp0, 1);
            pp0 += __shfl_xor_sync(0xffffffffu, pp0, 2);
            pp1 += __shfl_xor_sync(0xffffffffu, pp1, 1);
            pp1 += __shfl_xor_sync(0xffffffffu, pp1, 2);
            if (tq == 0) {
                float* php = sm + S_PHIP + buf * 128;
                php[r0 * 2 + whalf] = pp0;
                php[r1 * 2 + whalf] = pp1;
            }
            // agg: half2 loads — lane = 16*rh + cc handles cols (nhalf+2cc,+1), 8 rows
            const __half2* pm2 = (const __half2*)(smh + H_M2 + (mrow + 8 * rh) * 72 + nhalf + 2 * cc);
#pragma unroll
            for (int jj = 0; jj < 8; jj++) {
                float aj = __shfl_sync(0xffffffffu, attsOwn, 8 * rh + jj);
                float2 mv = __half22float2(pm2[jj * 36]);
                aggA += mv.x * aj;
                aggB += mv.y * aj;
            }
        }
        // NO tail barrier: MS is double-buffered; PHIP double-buffered;
        // M2/ATTP overwrite in next phase C is ordered by the next post-B full sync.
    }
    __syncthreads();   // all phase-E(3) PHIP writes visible
    // ---- tail: finalize tile-3 phi/coord, agg store, coord out, node update ----
    if (tid < 64) {
        int j = 192 + tid;
        const float* php = sm + S_PHIP + 128;   // buf of tile 3 = 1
        float p = php[tid * 2] + php[tid * 2 + 1];
        float em = (j == i) ? 0.f : nmi * __ldg(nmb + j);
        float ph = tanhf(p) * CRANGE * em;
        sm[S_CA0 + tid] += sm[S_DIFFN + j * 3 + 0] * ph;
        sm[S_CA1 + tid] += sm[S_DIFFN + j * 3 + 1] * ph;
        sm[S_CA2 + tid] += sm[S_DIFFN + j * 3 + 2] * ph;
    }
    aggA += __shfl_xor_sync(0xffffffffu, aggA, 16);
    aggB += __shfl_xor_sync(0xffffffffu, aggB, 16);
    if (lane < 16) {
        float2 v; v.x = aggA; v.y = aggB;
        *(float2*)(sm + S_AGGP + (wid & 3) * 64 + nhalf + 2 * lane) = v;
    }
    __syncthreads();
    if (tid < 64) {
        sm[S_UPD + tid] = g_h[bn * 64 + tid];
        sm[S_UPD + 64 + tid] = sm[S_AGGP + tid] + sm[S_AGGP + 64 + tid]
                             + sm[S_AGGP + 128 + tid] + sm[S_AGGP + 192 + tid];
    }
    __syncthreads();
    if (tid < 3) {
        float s = 0.f;
#pragma unroll
        for (int q = 0; q < 64; q++) s += sm[S_CA0 + tid * 64 + q];
        cOut[bn * 3 + tid] = (sm[S_COORD + i * 3 + tid] + s) * nmi;
    }
    if (l < NL - 1) {
        int k = tid >> 2, q = tid & 3;
        {
            const float* w1 = nw1 + ((size_t)l * 64 + k) * 128 + q * 32;
            const float* src = sm + S_UPD + q * 32;
            float acc = 0.f;
#pragma unroll
            for (int c = 0; c < 32; c++) acc += w1[c] * src[c];
            acc += __shfl_xor_sync(0xffffffffu, acc, 1);
            acc += __shfl_xor_sync(0xffffffffu, acc, 2);
            if (q == 0) sm[S_UPD + 128 + k] = siluf(acc + nb1[l * 64 + k]);
        }
        __syncthreads();
        {
            const float* w2 = nw2 + ((size_t)l * 64 + k) * 64 + q * 16;
            const float* stp = sm + S_UPD + 128 + q * 16;
            float u = 0.f;
#pragma unroll
            for (int c = 0; c < 16; c++) u += w2[c] * stp[c];
            u += __shfl_xor_sync(0xffffffffu, u, 1);
            u += __shfl_xor_sync(0xffffffffu, u, 2);
            if (q == 0) {
                float hn = (sm[S_UPD + k] + u + nb2[l * 64 + k]) * nmi;
                sm[S_UPD + 192 + k] = hn;
                g_h[bn * 64 + k] = hn;
            }
        }
        __syncthreads();
        {
            const float* w1n = ew1 + ((size_t)(l + 1) * 64 + k) * 130 + q * 16;
            const float* hp = sm + S_UPD + 192 + q * 16;
            float a = 0.f, bv = 0.f;
#pragma unroll
            for (int c = 0; c < 16; c++) { a += w1n[c] * hp[c]; bv += w1n[64 + c] * hp[c]; }
            a  += __shfl_xor_sync(0xffffffffu, a, 1);
            a  += __shfl_xor_sync(0xffffffffu, a, 2);
            bv += __shfl_xor_sync(0xffffffffu, bv, 1);
            bv += __shfl_xor_sync(0xffffffffu, bv, 2);
            if (q == 0) {
                g_H1A[bn * 64 + k] = a + eb1[(l + 1) * 64 + k];
                h1bOut[bn * 64 + k] = __float2half_rn(bv);
            }
        }
    }
}

// ---------------- final: vel + remove mean ----------------
__global__ void k_final(const float* __restrict__ nm, float* __restrict__ out) {
    int b = blockIdx.x;
    int j = threadIdx.x;                     // 256 threads
    __shared__ float rs[256 * 4];
    int bn = b * 256 + j;
    float nmv = nm[bn];
    float v0 = (g_coordA[bn * 3 + 0] - g_x0[bn * 3 + 0]) * nmv;
    float v1 = (g_coordA[bn * 3 + 1] - g_x0[bn * 3 + 1]) * nmv;
    float v2 = (g_coordA[bn * 3 + 2] - g_x0[bn * 3 + 2]) * nmv;
    rs[j] = v0; rs[256 + j] = v1; rs[512 + j] = v2; rs[768 + j] = nmv;
    __syncthreads();
    for (int o = 128; o > 0; o >>= 1) {
        if (j < o) {
            rs[j] += rs[j + o];
            rs[256 + j] += rs[256 + j + o];
            rs[512 + j] += rs[512 + j + o];
            rs[768 + j] += rs[768 + j + o];
        }
        __syncthreads();
    }
    float inv = 1.f / rs[768];
    float m0 = rs[0] * inv, m1 = rs[256] * inv, m2 = rs[512] * inv;
    out[b * 768 + j * 3 + 0] = v0 - m0 * nmv;
    out[b * 768 + j * 3 + 1] = v1 - m1 * nmv;
    out[b * 768 + j * 3 + 2] = v2 - m2 * nmv;
}

// ---------------- launch ----------------
extern "C" void kernel_launch(void* const* d_in, const int* in_sizes, int n_in,
                              void* d_out, int out_size) {
    (void)in_sizes; (void)n_in; (void)out_size;
    const float* t     = (const float*)d_in[0];
    const float* x     = (const float*)d_in[1];
    const float* at    = (const float*)d_in[2];
    const float* aat   = (const float*)d_in[3];
    const float* aap   = (const float*)d_in[4];
    const float* nm    = (const float*)d_in[5];
    const float* emb_w = (const float*)d_in[6];
    const float* emb_b = (const float*)d_in[7];
    const float* ew1   = (const float*)d_in[8];
    const float* eb1   = (const float*)d_in[9];
    const float* ew2   = (const float*)d_in[10];
    const float* eb2   = (const float*)d_in[11];
    const float* nw1   = (const float*)d_in[12];
    const float* nb1   = (const float*)d_in[13];
    const float* nw2   = (const float*)d_in[14];
    const float* nb2   = (const float*)d_in[15];
    const float* cw1   = (const float*)d_in[16];
    const float* cb1   = (const float*)d_in[17];
    const float* aw    = (const float*)d_in[18];
    const float* ab    = (const float*)d_in[19];
    const float* cw2   = (const float*)d_in[20];
    float* out = (float*)d_out;

    cudaFuncSetAttribute(k_edge, cudaFuncAttributeMaxDynamicSharedMemorySize, SMEM_BYTES);

    k_wconv<<<NL, 256>>>(ew2, cw1);
    k_init<<<BN, 256>>>(t, x, at, aat, aap, nm, emb_w, emb_b, ew1, eb1);
    for (int l = 0; l < NL; l++) {
        k_edge<<<BN, 256, SMEM_BYTES>>>(l, ew1, eb1, ew2, eb2,
                                        nw1, nb1, nw2, nb2, cw1, cb1, aw, ab, cw2, nm);
    }
    k_final<<<NB, 256>>>(nm, out);
}

// round 17
// speedup vs baseline: 1.0079x; 1.0075x over previous
#include <cuda_runtime.h>
#include <cuda_fp16.h>
#include <cstdint>

#define NB 8
#define NN 256
#define BN (NB*NN)          // 2048 nodes
#define HD 64
#define NL 4
#define CRANGE 3.75f        // 15.0 / 4 layers

// ---------------- device scratch ----------------
__device__ __align__(16) float g_h[BN*HD];
__device__ __align__(16) float g_H1A[BN*HD];
__device__ __align__(16) float g_H1B[2][BN*HD];
__device__ __align__(16) float g_E0[BN*NN];
__device__ __align__(16) float g_coordA[BN*3];
__device__ __align__(16) float g_coordB[BN*3];
__device__ __align__(16) float g_x0[BN*3];
__device__ __align__(16) __half g_W2h[NL][64*72];
__device__ __align__(16) __half g_C1h[NL][64*72];

__device__ __forceinline__ float tanh_ap(float x) {
    float y; asm("tanh.approx.f32 %0, %1;" : "=f"(y) : "f"(x)); return y;
}
__device__ __forceinline__ float silu_h(float x) {
    return x * fmaf(0.5f, tanh_ap(0.5f * x), 0.5f);
}
__device__ __forceinline__ float sigm_h(float x) {
    return fmaf(0.5f, tanh_ap(0.5f * x), 0.5f);
}
__device__ __forceinline__ float siluf(float x) {
    return __fdividef(x, 1.f + __expf(-x));
}

// ---------------- HMMA helpers ----------------
#define LDSM4(r0,r1,r2,r3, addr) \
    asm volatile("ldmatrix.sync.aligned.m8n8.x4.shared.b16 {%0,%1,%2,%3}, [%4];" \
        : "=r"(r0), "=r"(r1), "=r"(r2), "=r"(r3) : "r"(addr))

#define MMA16816(d, a0,a1,a2,a3, b0,b1) \
    asm volatile("mma.sync.aligned.m16n8k16.row.col.f32.f16.f16.f32 " \
        "{%0,%1,%2,%3}, {%4,%5,%6,%7}, {%8,%9}, {%0,%1,%2,%3};" \
        : "+f"(d[0]), "+f"(d[1]), "+f"(d[2]), "+f"(d[3]) \
        : "r"(a0), "r"(a1), "r"(a2), "r"(a3), "r"(b0), "r"(b1))

#define PAIR_BAR(id) asm volatile("bar.sync %0, 64;" :: "r"(id) : "memory")

// ---------------- init: x0, coord, embedding, layer-0 H1A/H1B, E0, weight conv ----------------
__global__ void k_init(const float* __restrict__ t, const float* __restrict__ x,
                       const float* __restrict__ at, const float* __restrict__ aat,
                       const float* __restrict__ aap, const float* __restrict__ nm,
                       const float* __restrict__ emb_w, const float* __restrict__ emb_b,
                       const float* __restrict__ ew1, const float* __restrict__ eb1,
                       const float* __restrict__ ew2, const float* __restrict__ cw1) {
    int bn = blockIdx.x;
    int b = bn >> 8, i = bn & 255;
    int tid = threadIdx.x;                   // 256 threads
    __shared__ float sh[HD];
    // fold former k_wconv: CTAs 0..3 convert weights for layer = blockIdx.x
    if (bn < NL) {
        const float* w2g = ew2 + (size_t)bn * 4096;
        const float* c1g = cw1 + (size_t)bn * 4096;
        for (int e = tid; e < 4096; e += 256) {
            int r = e >> 6, c = e & 63;
            g_W2h[bn][r * 72 + c] = __float2half_rn(w2g[e]);
            g_C1h[bn][r * 72 + c] = __float2half_rn(c1g[e]);
        }
    }
    float nmv = nm[bn];
    float xi0 = x[b * 768 + i * 3 + 0] * nmv;
    float xi1 = x[b * 768 + i * 3 + 1] * nmv;
    float xi2 = x[b * 768 + i * 3 + 2] * nmv;
    if (tid < 3) {
        float v = x[b * 768 + i * 3 + tid] * nmv;
        g_x0[bn * 3 + tid] = v;
        g_coordA[bn * 3 + tid] = v;
    }
    {
        float nmj = nm[b * 256 + tid];
        float dx = xi0 - x[b * 768 + tid * 3 + 0] * nmj;
        float dy = xi1 - x[b * 768 + tid * 3 + 1] * nmj;
        float dz = xi2 - x[b * 768 + tid * 3 + 2] * nmj;
        g_E0[bn * 256 + tid] = dx * dx + dy * dy + dz * dz;
    }
    if (tid < 64) {
        float f0 = at[bn] * nmv, f1 = aat[bn] * nmv, f2 = aap[bn] * nmv, f3 = t[b] * nmv;
        float h = emb_b[tid] + emb_w[tid * 4 + 0] * f0 + emb_w[tid * 4 + 1] * f1
                + emb_w[tid * 4 + 2] * f2 + emb_w[tid * 4 + 3] * f3;
        g_h[bn * HD + tid] = h;
        sh[tid] = h;
    }
    __syncthreads();
    int k = tid >> 2, q = tid & 3;
    const float* w1 = ew1 + (size_t)k * 130 + q * 16;     // layer 0
    const float* hp = sh + q * 16;
    float a = 0.f, bv = 0.f;
#pragma unroll
    for (int c = 0; c < 16; c++) { a += w1[c] * hp[c]; bv += w1[64 + c] * hp[c]; }
    a  += __shfl_xor_sync(0xffffffffu, a, 1);
    a  += __shfl_xor_sync(0xffffffffu, a, 2);
    bv += __shfl_xor_sync(0xffffffffu, bv, 1);
    bv += __shfl_xor_sync(0xffffffffu, bv, 2);
    if (q == 0) {
        g_H1A[bn * 64 + k] = a + eb1[k];
        g_H1B[0][bn * 64 + k] = bv;
    }
}

// ---------------- edge kernel smem layout ----------------
// fp16 tiles (half indices), stride 72 halfs
#define H_W2   0
#define H_C1   4608
#define H_MS   9216
#define H_M2   13824
// fp32 region (float indices); halves occupy floats [0, 9216)
#define S_COORD 9216
#define S_RADE  9984
#define S_DIFFN 10496
#define S_H1A   11264
#define S_WR    11328
#define S_WE    11392
#define S_B2    11456
#define S_CB1   11520
#define S_AW    11584
#define S_CW2   11648
#define S_ATTP  11712
#define S_PHIP  11840
#define S_CA0   11968
#define S_CA1   12032
#define S_CA2   12096
#define S_AGGP  12160
#define S_UPD   12416
#define SMEM_FLOATS 12672
#define SMEM_BYTES  (SMEM_FLOATS * 4)

__global__ void __launch_bounds__(256, 2)
k_edge(int l,
       const float* __restrict__ ew1, const float* __restrict__ eb1,
       const float* __restrict__ ew2, const float* __restrict__ eb2,
       const float* __restrict__ nw1, const float* __restrict__ nb1,
       const float* __restrict__ nw2, const float* __restrict__ nb2,
       const float* __restrict__ cw1, const float* __restrict__ cb1,
       const float* __restrict__ aw,  const float* __restrict__ ab,
       const float* __restrict__ cw2, const float* __restrict__ nm) {
    extern __shared__ float sm[];
    __half* smh = (__half*)sm;
    int ping = l & 1;
    const float* cIn = ping ? g_coordB : g_coordA;
    float* cOut = ping ? g_coordA : g_coordB;
    const float* h1bIn = g_H1B[ping];
    float* h1bOut = g_H1B[ping ^ 1];

    int tid = threadIdx.x;
    int wid = tid >> 5, lane = tid & 31;
    int t4 = lane >> 2, tq = lane & 3;
    int rh = lane >> 4, cc = lane & 15;     // agg lane remap
    int mrow = (wid & 3) << 4;
    int nhalf = (wid >> 2) << 5;
    int whalf = wid >> 2;
    int pairId = 1 + (wid & 3);
    int bn = blockIdx.x;
    int b = bn >> 8, i = bn & 255;

    // ---- stage weights (pre-converted fp16, uint4 copy) + vectors + coords ----
    {
        const uint4* sw2 = (const uint4*)(g_W2h[l]);
        const uint4* sc1 = (const uint4*)(g_C1h[l]);
        uint4* dw2 = (uint4*)(smh + H_W2);
        uint4* dc1 = (uint4*)(smh + H_C1);
        for (int e = tid; e < 576; e += 256) { dw2[e] = sw2[e]; dc1[e] = sc1[e]; }
    }
    if (tid < 64) {
        sm[S_WR  + tid] = ew1[((size_t)l * 64 + tid) * 130 + 128];
        sm[S_WE  + tid] = ew1[((size_t)l * 64 + tid) * 130 + 129];
        sm[S_B2  + tid] = eb2[l * 64 + tid];
        sm[S_CB1 + tid] = cb1[l * 64 + tid];
        sm[S_AW  + tid] = aw[l * 64 + tid];
        sm[S_CW2 + tid] = cw2[l * 64 + tid];
        sm[S_H1A + tid] = g_H1A[bn * 64 + tid];
        sm[S_CA0 + tid] = 0.f;
        sm[S_CA1 + tid] = 0.f;
        sm[S_CA2 + tid] = 0.f;
    }
    for (int e = tid; e < 768; e += 256) sm[S_COORD + e] = cIn[b * 768 + e];
    float attb = ab[l];
    float nmi = nm[bn];
    __syncthreads();

    // ---- geometry + (rad,e0) for ALL 256 j (once) ----
    {
        float cix = sm[S_COORD + i * 3], ciy = sm[S_COORD + i * 3 + 1], ciz = sm[S_COORD + i * 3 + 2];
        int j = tid;
        float dx = cix - sm[S_COORD + j * 3];
        float dy = ciy - sm[S_COORD + j * 3 + 1];
        float dz = ciz - sm[S_COORD + j * 3 + 2];
        float rad = dx * dx + dy * dy + dz * dz;
        float inv = 1.f / (sqrtf(rad + 1e-8f) + 1.f);
        float2 re; re.x = rad; re.y = __ldg(g_E0 + (size_t)bn * 256 + j);
        *(float2*)(sm + S_RADE + j * 2) = re;
        sm[S_DIFFN + j * 3 + 0] = dx * inv;
        sm[S_DIFFN + j * 3 + 1] = dy * inv;
        sm[S_DIFFN + j * 3 + 2] = dz * inv;
    }
    __syncthreads();

    // ---- ldmatrix lane addressing ----
    uint32_t sbase = (uint32_t)__cvta_generic_to_shared((void*)sm);
    int ar = (lane & 7) + ((lane >> 3) & 1) * 8;
    int ac = (lane >> 4) * 8;
    uint32_t aoff = (uint32_t)(((mrow + ar) * 72 + ac) * 2);
    int br = (lane & 7) + ((lane >> 4) ? 8 : 0);
    int bc = ((lane >> 3) & 1) * 8;
    uint32_t boff = (uint32_t)(((nhalf + br) * 72 + bc) * 2);
    uint32_t aMS = sbase + H_MS * 2 + aoff;
    uint32_t aM2 = sbase + H_M2 * 2 + aoff;
    uint32_t bW2 = sbase + H_W2 * 2 + boff;
    uint32_t bC1 = sbase + H_C1 * 2 + boff;

    // ---- hoist B fragments (tile-invariant) into registers ----
    uint32_t fw[4][2][4], fc[4][2][4];
#pragma unroll
    for (int kk = 0; kk < 4; kk++)
#pragma unroll
        for (int ntp = 0; ntp < 2; ntp++) {
            LDSM4(fw[kk][ntp][0], fw[kk][ntp][1], fw[kk][ntp][2], fw[kk][ntp][3],
                  bW2 + ntp * 2304 + kk * 32);
            LDSM4(fc[kk][ntp][0], fc[kk][ntp][1], fc[kk][ntp][2], fc[kk][ntp][3],
                  bC1 + ntp * 2304 + kk * 32);
        }

    float aggA = 0.f, aggB = 0.f;   // cols nhalf+2cc, +1; rows mrow+8rh..+7
    const float* nmb = nm + b * 256;
    int r0 = mrow + t4, r1 = r0 + 8;

    for (int tile = 0; tile < 4; tile++) {
        int j0 = tile << 6;
        // ---- phase F (finalize previous tile's phi/coord) + phase B ----
        if (tile > 0 && tid < 64) {
            int j = j0 - 64 + tid;
            float p = sm[S_PHIP + tid * 2] + sm[S_PHIP + tid * 2 + 1];
            float em = (j == i) ? 0.f : nmi * __ldg(nmb + j);
            float ph = tanhf(p) * CRANGE * em;
            sm[S_CA0 + tid] += sm[S_DIFFN + j * 3 + 0] * ph;
            sm[S_CA1 + tid] += sm[S_DIFFN + j * 3 + 1] * ph;
            sm[S_CA2 + tid] += sm[S_DIFFN + j * 3 + 2] * ph;
        }
        const float* h1bg = h1bIn + ((size_t)(b * 256 + j0)) * 64;
#pragma unroll
        for (int it = 0; it < 4; it++) {
            int p = tid + it * 256;
            int jj = p >> 4, q4 = (p & 15) * 4;
            float4 hb = *(const float4*)(h1bg + jj * 64 + q4);
            float2 re = *(const float2*)(sm + S_RADE + (j0 + jj) * 2);
            float v0 = silu_h(sm[S_H1A + q4]     + hb.x + sm[S_WR + q4]     * re.x + sm[S_WE + q4]     * re.y);
            float v1 = silu_h(sm[S_H1A + q4 + 1] + hb.y + sm[S_WR + q4 + 1] * re.x + sm[S_WE + q4 + 1] * re.y);
            float v2 = silu_h(sm[S_H1A + q4 + 2] + hb.z + sm[S_WR + q4 + 2] * re.x + sm[S_WE + q4 + 2] * re.y);
            float v3 = silu_h(sm[S_H1A + q4 + 3] + hb.w + sm[S_WR + q4 + 3] * re.x + sm[S_WE + q4 + 3] * re.y);
            __half2 ha = __floats2half2_rn(v0, v1);
            __half2 hb2 = __floats2half2_rn(v2, v3);
            uint2 u; u.x = *(uint32_t*)&ha; u.y = *(uint32_t*)&hb2;
            *(uint2*)(smh + H_MS + jj * 72 + q4) = u;       // single STS.64
        }
        __syncthreads();
        // ---- phase C: GEMM1 (HMMA, B from regs) + epilogue ----
        {
            float acc[4][4];
#pragma unroll
            for (int nt = 0; nt < 4; nt++)
#pragma unroll
                for (int r = 0; r < 4; r++) acc[nt][r] = 0.f;
#pragma unroll
            for (int kk = 0; kk < 4; kk++) {
                uint32_t a0, a1, a2, a3;
                LDSM4(a0, a1, a2, a3, aMS + kk * 32);
#pragma unroll
                for (int ntp = 0; ntp < 2; ntp++) {
                    MMA16816(acc[2 * ntp],     a0, a1, a2, a3, fw[kk][ntp][0], fw[kk][ntp][1]);
                    MMA16816(acc[2 * ntp + 1], a0, a1, a2, a3, fw[kk][ntp][2], fw[kk][ntp][3]);
                }
            }
            float ap0 = 0.f, ap1 = 0.f;
#pragma unroll
            for (int nt = 0; nt < 4; nt++) {
                int c0 = nhalf + nt * 8 + 2 * tq;
                float b2a = sm[S_B2 + c0], b2b = sm[S_B2 + c0 + 1];
                float m00 = silu_h(acc[nt][0] + b2a);
                float m01 = silu_h(acc[nt][1] + b2b);
                float m10 = silu_h(acc[nt][2] + b2a);
                float m11 = silu_h(acc[nt][3] + b2b);
                *(__half2*)(smh + H_M2 + r0 * 72 + c0) = __floats2half2_rn(m00, m01);
                *(__half2*)(smh + H_M2 + r1 * 72 + c0) = __floats2half2_rn(m10, m11);
                float awa = sm[S_AW + c0], awb = sm[S_AW + c0 + 1];
                ap0 += m00 * awa + m01 * awb;
                ap1 += m10 * awa + m11 * awb;
            }
            ap0 += __shfl_xor_sync(0xffffffffu, ap0, 1);
            ap0 += __shfl_xor_sync(0xffffffffu, ap0, 2);
            ap1 += __shfl_xor_sync(0xffffffffu, ap1, 1);
            ap1 += __shfl_xor_sync(0xffffffffu, ap1, 2);
            if (tq == 0) {
                sm[S_ATTP + r0 * 2 + whalf] = ap0;
                sm[S_ATTP + r1 * 2 + whalf] = ap1;
            }
        }
        PAIR_BAR(pairId);   // phase E only touches pair-local M2/ATTP
        // ---- phase E: atts in-warp, GEMM2 (HMMA, B from regs), phi, agg ----
        {
            float attsOwn = 0.f;
            if (lane < 16) {
                int r = mrow + lane;
                int j = j0 + r;
                float dot = sm[S_ATTP + r * 2] + sm[S_ATTP + r * 2 + 1] + attb;
                float em = (j == i) ? 0.f : nmi * __ldg(nmb + j);
                attsOwn = sigm_h(dot) * em;
            }
            float sr0 = __shfl_sync(0xffffffffu, attsOwn, t4);
            float sr1 = __shfl_sync(0xffffffffu, attsOwn, t4 + 8);

            float acc[4][4];
#pragma unroll
            for (int nt = 0; nt < 4; nt++)
#pragma unroll
                for (int r = 0; r < 4; r++) acc[nt][r] = 0.f;
#pragma unroll
            for (int kk = 0; kk < 4; kk++) {
                uint32_t a0, a1, a2, a3;
                LDSM4(a0, a1, a2, a3, aM2 + kk * 32);
#pragma unroll
                for (int ntp = 0; ntp < 2; ntp++) {
                    MMA16816(acc[2 * ntp],     a0, a1, a2, a3, fc[kk][ntp][0], fc[kk][ntp][1]);
                    MMA16816(acc[2 * ntp + 1], a0, a1, a2, a3, fc[kk][ntp][2], fc[kk][ntp][3]);
                }
            }
            float pp0 = 0.f, pp1 = 0.f;
#pragma unroll
            for (int nt = 0; nt < 4; nt++) {
                int c0 = nhalf + nt * 8 + 2 * tq;
                float cba = sm[S_CB1 + c0], cbb = sm[S_CB1 + c0 + 1];
                float cwa = sm[S_CW2 + c0], cwb = sm[S_CW2 + c0 + 1];
                pp0 += silu_h(fmaf(sr0, acc[nt][0], cba)) * cwa
                     + silu_h(fmaf(sr0, acc[nt][1], cbb)) * cwb;
                pp1 += silu_h(fmaf(sr1, acc[nt][2], cba)) * cwa
                     + silu_h(fmaf(sr1, acc[nt][3], cbb)) * cwb;
            }
            pp0 += __shfl_xor_sync(0xffffffffu, pp0, 1);
            pp0 += __shfl_xor_sync(0xffffffffu, pp0, 2);
            pp1 += __shfl_xor_sync(0xffffffffu, pp1, 1);
            pp1 += __shfl_xor_sync(0xffffffffu, pp1, 2);
            if (tq == 0) {
                sm[S_PHIP + r0 * 2 + whalf] = pp0;
                sm[S_PHIP + r1 * 2 + whalf] = pp1;
            }
            // agg: half2 loads — lane = 16*rh + cc handles cols (nhalf+2cc,+1), 8 rows
            const __half2* pm2 = (const __half2*)(smh + H_M2 + (mrow + 8 * rh) * 72 + nhalf + 2 * cc);
#pragma unroll
            for (int jj = 0; jj < 8; jj++) {
                float aj = __shfl_sync(0xffffffffu, attsOwn, 8 * rh + jj);
                float2 mv = __half22float2(pm2[jj * 36]);
                aggA += mv.x * aj;
                aggB += mv.y * aj;
            }
        }
        __syncthreads();
    }
    // ---- tail: finalize tile-3 phi/coord, agg store, coord out, node update ----
    if (tid < 64) {
        int j = 192 + tid;
        float p = sm[S_PHIP + tid * 2] + sm[S_PHIP + tid * 2 + 1];
        float em = (j == i) ? 0.f : nmi * __ldg(nmb + j);
        float ph = tanhf(p) * CRANGE * em;
        sm[S_CA0 + tid] += sm[S_DIFFN + j * 3 + 0] * ph;
        sm[S_CA1 + tid] += sm[S_DIFFN + j * 3 + 1] * ph;
        sm[S_CA2 + tid] += sm[S_DIFFN + j * 3 + 2] * ph;
    }
    aggA += __shfl_xor_sync(0xffffffffu, aggA, 16);
    aggB += __shfl_xor_sync(0xffffffffu, aggB, 16);
    if (lane < 16) {
        float2 v; v.x = aggA; v.y = aggB;
        *(float2*)(sm + S_AGGP + (wid & 3) * 64 + nhalf + 2 * lane) = v;
    }
    __syncthreads();
    if (tid < 64) {
        sm[S_UPD + tid] = g_h[bn * 64 + tid];
        sm[S_UPD + 64 + tid] = sm[S_AGGP + tid] + sm[S_AGGP + 64 + tid]
                             + sm[S_AGGP + 128 + tid] + sm[S_AGGP + 192 + tid];
    }
    __syncthreads();
    if (tid < 3) {
        float s = 0.f;
#pragma unroll
        for (int q = 0; q < 64; q++) s += sm[S_CA0 + tid * 64 + q];
        cOut[bn * 3 + tid] = (sm[S_COORD + i * 3 + tid] + s) * nmi;
    }
    if (l < NL - 1) {
        int k = tid >> 2, q = tid & 3;
        {
            const float* w1 = nw1 + ((size_t)l * 64 + k) * 128 + q * 32;
            const float* src = sm + S_UPD + q * 32;
            float acc = 0.f;
#pragma unroll
            for (int c = 0; c < 32; c++) acc += w1[c] * src[c];
            acc += __shfl_xor_sync(0xffffffffu, acc, 1);
            acc += __shfl_xor_sync(0xffffffffu, acc, 2);
            if (q == 0) sm[S_UPD + 128 + k] = siluf(acc + nb1[l * 64 + k]);
        }
        __syncthreads();
        {
            const float* w2 = nw2 + ((size_t)l * 64 + k) * 64 + q * 16;
            const float* stp = sm + S_UPD + 128 + q * 16;
            float u = 0.f;
#pragma unroll
            for (int c = 0; c < 16; c++) u += w2[c] * stp[c];
            u += __shfl_xor_sync(0xffffffffu, u, 1);
            u += __shfl_xor_sync(0xffffffffu, u, 2);
            if (q == 0) {
                float hn = (sm[S_UPD + k] + u + nb2[l * 64 + k]) * nmi;
                sm[S_UPD + 192 + k] = hn;
                g_h[bn * 64 + k] = hn;
            }
        }
        __syncthreads();
        {
            const float* w1n = ew1 + ((size_t)(l + 1) * 64 + k) * 130 + q * 16;
            const float* hp = sm + S_UPD + 192 + q * 16;
            float a = 0.f, bv = 0.f;
#pragma unroll
            for (int c = 0; c < 16; c++) { a += w1n[c] * hp[c]; bv += w1n[64 + c] * hp[c]; }
            a  += __shfl_xor_sync(0xffffffffu, a, 1);
            a  += __shfl_xor_sync(0xffffffffu, a, 2);
            bv += __shfl_xor_sync(0xffffffffu, bv, 1);
            bv += __shfl_xor_sync(0xffffffffu, bv, 2);
            if (q == 0) {
                g_H1A[bn * 64 + k] = a + eb1[(l + 1) * 64 + k];
                h1bOut[bn * 64 + k] = bv;
            }
        }
    }
}

// ---------------- final: vel + remove mean ----------------
__global__ void k_final(const float* __restrict__ nm, float* __restrict__ out) {
    int b = blockIdx.x;
    int j = threadIdx.x;                     // 256 threads
    __shared__ float rs[256 * 4];
    int bn = b * 256 + j;
    float nmv = nm[bn];
    float v0 = (g_coordA[bn * 3 + 0] - g_x0[bn * 3 + 0]) * nmv;
    float v1 = (g_coordA[bn * 3 + 1] - g_x0[bn * 3 + 1]) * nmv;
    float v2 = (g_coordA[bn * 3 + 2] - g_x0[bn * 3 + 2]) * nmv;
    rs[j] = v0; rs[256 + j] = v1; rs[512 + j] = v2; rs[768 + j] = nmv;
    __syncthreads();
    for (int o = 128; o > 0; o >>= 1) {
        if (j < o) {
            rs[j] += rs[j + o];
            rs[256 + j] += rs[256 + j + o];
            rs[512 + j] += rs[512 + j + o];
            rs[768 + j] += rs[768 + j + o];
        }
        __syncthreads();
    }
    float inv = 1.f / rs[768];
    float m0 = rs[0] * inv, m1 = rs[256] * inv, m2 = rs[512] * inv;
    out[b * 768 + j * 3 + 0] = v0 - m0 * nmv;
    out[b * 768 + j * 3 + 1] = v1 - m1 * nmv;
    out[b * 768 + j * 3 + 2] = v2 - m2 * nmv;
}

// ---------------- launch ----------------
extern "C" void kernel_launch(void* const* d_in, const int* in_sizes, int n_in,
                              void* d_out, int out_size) {
    (void)in_sizes; (void)n_in; (void)out_size;
    const float* t     = (const float*)d_in[0];
    const float* x     = (const float*)d_in[1];
    const float* at    = (const float*)d_in[2];
    const float* aat   = (const float*)d_in[3];
    const float* aap   = (const float*)d_in[4];
    const float* nm    = (const float*)d_in[5];
    const float* emb_w = (const float*)d_in[6];
    const float* emb_b = (const float*)d_in[7];
    const float* ew1   = (const float*)d_in[8];
    const float* eb1   = (const float*)d_in[9];
    const float* ew2   = (const float*)d_in[10];
    const float* eb2   = (const float*)d_in[11];
    const float* nw1   = (const float*)d_in[12];
    const float* nb1   = (const float*)d_in[13];
    const float* nw2   = (const float*)d_in[14];
    const float* nb2   = (const float*)d_in[15];
    const float* cw1   = (const float*)d_in[16];
    const float* cb1   = (const float*)d_in[17];
    const float* aw    = (const float*)d_in[18];
    const float* ab    = (const float*)d_in[19];
    const float* cw2   = (const float*)d_in[20];
    float* out = (float*)d_out;

    cudaFuncSetAttribute(k_edge, cudaFuncAttributeMaxDynamicSharedMemorySize, SMEM_BYTES);

    k_init<<<BN, 256>>>(t, x, at, aat, aap, nm, emb_w, emb_b, ew1, eb1, ew2, cw1);
    for (int l = 0; l < NL; l++) {
        k_edge<<<BN, 256, SMEM_BYTES>>>(l, ew1, eb1, ew2, eb2,
                                        nw1, nb1, nw2, nb2, cw1, cb1, aw, ab, cw2, nm);
    }
    k_final<<<NB, 256>>>(nm, out);
}